// round 1
// baseline (speedup 1.0000x reference)
#include <cuda_runtime.h>
#include <math.h>

#define GM 65536
#define GK 768
#define GN 768

// Scratch for Q, K, V projections (allocation-free rule: __device__ globals).
__device__ float g_Q[(size_t)GM * GN];
__device__ float g_K[(size_t)GM * GN];
__device__ float g_V[(size_t)GM * GN];

// ---------------------------------------------------------------------------
// QKV projection: C = A @ W^T + bias.  A: [65536, 768] row-major,
// W: [768, 768] row-major ([N,K] -> NT GEMM, dot of rows).
// Block tile 128x64, BK=16, 256 threads, 8x4 per-thread micro-tile.
// ---------------------------------------------------------------------------
__global__ __launch_bounds__(256, 2)
void sgemm_qkv(const float* __restrict__ A,
               const float* __restrict__ W,
               const float* __restrict__ bias,
               int sel)
{
    float* __restrict__ C = (sel == 0) ? g_Q : (sel == 1) ? g_K : g_V;

    __shared__ float As[16][132];   // [k][m], padded
    __shared__ float Ws[16][68];    // [k][n], padded

    const int tid = threadIdx.x;
    const int bm  = blockIdx.y * 128;
    const int bn  = blockIdx.x * 64;
    const int tm  = tid >> 4;       // 0..15 -> rows tm*8..tm*8+7
    const int tn  = tid & 15;       // 0..15 -> cols tn*4..tn*4+3

    float acc[8][4];
#pragma unroll
    for (int i = 0; i < 8; i++)
#pragma unroll
        for (int j = 0; j < 4; j++) acc[i][j] = 0.f;

    for (int k0 = 0; k0 < GK; k0 += 16) {
        // A tile: 128 rows x 16 cols = 512 float4, 2 per thread
#pragma unroll
        for (int t = 0; t < 2; t++) {
            int f4 = tid + t * 256;
            int r  = f4 >> 2;
            int c4 = f4 & 3;
            float4 v = *(const float4*)(A + (size_t)(bm + r) * GK + k0 + c4 * 4);
            As[c4 * 4 + 0][r] = v.x;
            As[c4 * 4 + 1][r] = v.y;
            As[c4 * 4 + 2][r] = v.z;
            As[c4 * 4 + 3][r] = v.w;
        }
        // W tile: 64 rows x 16 cols = 256 float4, 1 per thread
        {
            int r  = tid >> 2;
            int c4 = tid & 3;
            float4 v = *(const float4*)(W + (size_t)(bn + r) * GK + k0 + c4 * 4);
            Ws[c4 * 4 + 0][r] = v.x;
            Ws[c4 * 4 + 1][r] = v.y;
            Ws[c4 * 4 + 2][r] = v.z;
            Ws[c4 * 4 + 3][r] = v.w;
        }
        __syncthreads();

#pragma unroll
        for (int k = 0; k < 16; k++) {
            float a[8], b[4];
#pragma unroll
            for (int i = 0; i < 8; i++) a[i] = As[k][tm * 8 + i];
#pragma unroll
            for (int j = 0; j < 4; j++) b[j] = Ws[k][tn * 4 + j];
#pragma unroll
            for (int i = 0; i < 8; i++)
#pragma unroll
                for (int j = 0; j < 4; j++)
                    acc[i][j] = fmaf(a[i], b[j], acc[i][j]);
        }
        __syncthreads();
    }

    float4 bb = *(const float4*)(bias + bn + tn * 4);
#pragma unroll
    for (int i = 0; i < 8; i++) {
        float4 o;
        o.x = acc[i][0] + bb.x;
        o.y = acc[i][1] + bb.y;
        o.z = acc[i][2] + bb.z;
        o.w = acc[i][3] + bb.w;
        *(float4*)(C + (size_t)(bm + tm * 8 + i) * GN + bn + tn * 4) = o;
    }
}

// ---------------------------------------------------------------------------
// Fused causal flash attention over the reinterpreted layout.
// Grid: (qtile=4, head=12, group=256). 256 threads = 16(tx) x 16(ty).
// Each CTA: 64 queries x full causal K range for one (group, head).
// Thread micro-tiles: S tile 4q x 4k (k = tx+16j), O tile 4q x 4d (d = tx*4+j).
// Row softmax stats reduced with 16-lane shuffles.
// ---------------------------------------------------------------------------
__global__ __launch_bounds__(256)
void flash_attn(float* __restrict__ O)
{
    extern __shared__ float sm[];
    float* Qs = sm;                 // [64][68]
    float* Ks = sm + 64 * 68;       // [64][68]
    float* Vs = sm + 2 * 64 * 68;   // [64][68]
    float* Ps = sm + 3 * 64 * 68;   // [64][68]

    const int tid = threadIdx.x;
    const int qt  = blockIdx.x;
    const int h   = blockIdx.y;
    const int g   = blockIdx.z;
    const int tx  = tid & 15;
    const int ty  = tid >> 4;
    const int qy  = ty * 4;
    const int colh = h * 64;
    const size_t qrow0 = (size_t)g * 256 + qt * 64;

    // Load Q tile (64 rows x 64 cols) -> Qs
#pragma unroll
    for (int t = 0; t < 4; t++) {
        int f4 = tid + t * 256;
        int r  = f4 >> 4;
        int c  = (f4 & 15) * 4;
        *(float4*)(Qs + r * 68 + c) =
            *(const float4*)(g_Q + (qrow0 + r) * 768 + colh + c);
    }

    float m_i[4], l_i[4], acc[4][4];
#pragma unroll
    for (int i = 0; i < 4; i++) {
        m_i[i] = -1e30f;
        l_i[i] = 0.f;
#pragma unroll
        for (int j = 0; j < 4; j++) acc[i][j] = 0.f;
    }

    for (int kt = 0; kt <= qt; kt++) {
        __syncthreads();   // guards Qs first use + Ks/Vs/Ps reuse
        const size_t krow0 = (size_t)g * 256 + kt * 64;
#pragma unroll
        for (int t = 0; t < 4; t++) {
            int f4 = tid + t * 256;
            int r  = f4 >> 4;
            int c  = (f4 & 15) * 4;
            *(float4*)(Ks + r * 68 + c) =
                *(const float4*)(g_K + (krow0 + r) * 768 + colh + c);
            *(float4*)(Vs + r * 68 + c) =
                *(const float4*)(g_V + (krow0 + r) * 768 + colh + c);
        }
        __syncthreads();

        // S = Q K^T  (thread: q rows qy..qy+3, k cols {tx, tx+16, tx+32, tx+48})
        float s[4][4];
#pragma unroll
        for (int i = 0; i < 4; i++)
#pragma unroll
            for (int j = 0; j < 4; j++) s[i][j] = 0.f;

#pragma unroll
        for (int dd = 0; dd < 64; dd += 4) {
            float4 qv[4], kv[4];
#pragma unroll
            for (int i = 0; i < 4; i++)
                qv[i] = *(const float4*)(Qs + (qy + i) * 68 + dd);
#pragma unroll
            for (int j = 0; j < 4; j++)
                kv[j] = *(const float4*)(Ks + (tx + 16 * j) * 68 + dd);
#pragma unroll
            for (int i = 0; i < 4; i++) {
                const float* qf = (const float*)&qv[i];
#pragma unroll
                for (int j = 0; j < 4; j++) {
                    const float* kf = (const float*)&kv[j];
#pragma unroll
                    for (int u = 0; u < 4; u++)
                        s[i][j] = fmaf(qf[u], kf[u], s[i][j]);
                }
            }
        }

        const float scale = 0.125f;   // d^-0.5, d=64
#pragma unroll
        for (int i = 0; i < 4; i++)
#pragma unroll
            for (int j = 0; j < 4; j++) {
                s[i][j] *= scale;
                if (kt == qt && (tx + 16 * j) > (qy + i)) s[i][j] = -1e30f;
            }

        // Row max across this thread's 4 k, then across the 16 tx lanes
        float mt[4];
#pragma unroll
        for (int i = 0; i < 4; i++)
            mt[i] = fmaxf(fmaxf(s[i][0], s[i][1]), fmaxf(s[i][2], s[i][3]));
#pragma unroll
        for (int off = 8; off >= 1; off >>= 1)
#pragma unroll
            for (int i = 0; i < 4; i++)
                mt[i] = fmaxf(mt[i], __shfl_xor_sync(0xffffffffu, mt[i], off));

        float p[4][4], rs[4];
#pragma unroll
        for (int i = 0; i < 4; i++) {
            float mnew = fmaxf(m_i[i], mt[i]);
            float corr = __expf(m_i[i] - mnew);
            m_i[i] = mnew;
            float r0 = 0.f;
#pragma unroll
            for (int j = 0; j < 4; j++) {
                p[i][j] = __expf(s[i][j] - mnew);
                r0 += p[i][j];
            }
            rs[i] = r0;
            l_i[i] *= corr;
#pragma unroll
            for (int j = 0; j < 4; j++) acc[i][j] *= corr;
        }
#pragma unroll
        for (int off = 8; off >= 1; off >>= 1)
#pragma unroll
            for (int i = 0; i < 4; i++)
                rs[i] += __shfl_xor_sync(0xffffffffu, rs[i], off);
#pragma unroll
        for (int i = 0; i < 4; i++) l_i[i] += rs[i];

        // Stage P for the PV GEMM
#pragma unroll
        for (int i = 0; i < 4; i++)
#pragma unroll
            for (int j = 0; j < 4; j++)
                Ps[(qy + i) * 68 + tx + 16 * j] = p[i][j];
        __syncthreads();

        // acc += P @ V  (thread: q rows qy..qy+3, d cols tx*4..tx*4+3)
#pragma unroll
        for (int kk = 0; kk < 64; kk += 4) {
            float4 pv[4], vv[4];
#pragma unroll
            for (int i = 0; i < 4; i++)
                pv[i] = *(const float4*)(Ps + (qy + i) * 68 + kk);
#pragma unroll
            for (int t = 0; t < 4; t++)
                vv[t] = *(const float4*)(Vs + (kk + t) * 68 + tx * 4);
#pragma unroll
            for (int i = 0; i < 4; i++) {
                const float* pf = (const float*)&pv[i];
#pragma unroll
                for (int t = 0; t < 4; t++) {
                    const float* vt = (const float*)&vv[t];
#pragma unroll
                    for (int j = 0; j < 4; j++)
                        acc[i][j] = fmaf(pf[t], vt[j], acc[i][j]);
                }
            }
        }
    }

    // Epilogue: normalize and store
#pragma unroll
    for (int i = 0; i < 4; i++) {
        float inv = 1.0f / l_i[i];
        float4 o;
        o.x = acc[i][0] * inv;
        o.y = acc[i][1] * inv;
        o.z = acc[i][2] * inv;
        o.w = acc[i][3] * inv;
        *(float4*)(O + (qrow0 + qy + i) * 768 + colh + tx * 4) = o;
    }
}

// ---------------------------------------------------------------------------
extern "C" void kernel_launch(void* const* d_in, const int* in_sizes, int n_in,
                              void* d_out, int out_size)
{
    const float* X  = (const float*)d_in[0];
    const float* Wq = (const float*)d_in[1];
    const float* bq = (const float*)d_in[2];
    const float* Wk = (const float*)d_in[3];
    const float* bk = (const float*)d_in[4];
    const float* Wv = (const float*)d_in[5];
    const float* bv = (const float*)d_in[6];
    float* O = (float*)d_out;

    dim3 ggrid(GN / 64, GM / 128);
    sgemm_qkv<<<ggrid, 256>>>(X, Wq, bq, 0);
    sgemm_qkv<<<ggrid, 256>>>(X, Wk, bk, 1);
    sgemm_qkv<<<ggrid, 256>>>(X, Wv, bv, 2);

    const int attn_smem = 4 * 64 * 68 * (int)sizeof(float);  // 69632 B
    cudaFuncSetAttribute(flash_attn,
                         cudaFuncAttributeMaxDynamicSharedMemorySize, attn_smem);
    dim3 agrid(4, 12, 256);
    flash_attn<<<agrid, 256, attn_smem>>>(O);
}

// round 6
// speedup vs baseline: 2.1733x; 2.1733x over previous
#include <cuda_runtime.h>
#include <cuda_bf16.h>
#include <cstdint>
#include <math.h>

#define GM 65536
#define GK 768
#define GN 768

// ---------------------------------------------------------------------------
// Device scratch (allocation-free rule: __device__ globals)
// ---------------------------------------------------------------------------
__device__ float g_Q[(size_t)GM * GN];
__device__ float g_K[(size_t)GM * GN];
__device__ float g_V[(size_t)GM * GN];
__device__ __nv_bfloat16 g_Xhi[(size_t)GM * GK];
__device__ __nv_bfloat16 g_Xlo[(size_t)GM * GK];
__device__ __nv_bfloat16 g_Whi[3][(size_t)GN * GK];
__device__ __nv_bfloat16 g_Wlo[3][(size_t)GN * GK];

// ---------------------------------------------------------------------------
// Baseline-ISA helpers (compute_103-safe: no tcgen05 / TMEM)
// ---------------------------------------------------------------------------
__device__ __forceinline__ uint32_t smem_u32(const void* p) {
    uint32_t a;
    asm("{ .reg .u64 t; cvta.to.shared.u64 t, %1; cvt.u32.u64 %0, t; }"
        : "=r"(a) : "l"(p));
    return a;
}

__device__ __forceinline__ void cp_async16(uint32_t saddr, const void* gptr) {
    asm volatile("cp.async.cg.shared.global [%0], [%1], 16;"
                 :: "r"(saddr), "l"(gptr) : "memory");
}
#define CP_COMMIT() asm volatile("cp.async.commit_group;" ::: "memory")
#define CP_WAIT1()  asm volatile("cp.async.wait_group 1;" ::: "memory")

__device__ __forceinline__ void ldsm_x4(uint32_t* r, uint32_t addr) {
    asm volatile("ldmatrix.sync.aligned.m8n8.x4.shared.b16 {%0,%1,%2,%3}, [%4];"
                 : "=r"(r[0]), "=r"(r[1]), "=r"(r[2]), "=r"(r[3]) : "r"(addr));
}
__device__ __forceinline__ void ldsm_x2(uint32_t* r, uint32_t addr) {
    asm volatile("ldmatrix.sync.aligned.m8n8.x2.shared.b16 {%0,%1}, [%2];"
                 : "=r"(r[0]), "=r"(r[1]) : "r"(addr));
}
__device__ __forceinline__ void mma16816(float* c, const uint32_t* a, const uint32_t* b) {
    asm volatile(
        "mma.sync.aligned.m16n8k16.row.col.f32.bf16.bf16.f32 "
        "{%0,%1,%2,%3}, {%4,%5,%6,%7}, {%8,%9}, {%0,%1,%2,%3};"
        : "+f"(c[0]), "+f"(c[1]), "+f"(c[2]), "+f"(c[3])
        : "r"(a[0]), "r"(a[1]), "r"(a[2]), "r"(a[3]), "r"(b[0]), "r"(b[1]));
}

// ---------------------------------------------------------------------------
// Split conversion: x -> bf16 hi + bf16 lo
// ---------------------------------------------------------------------------
__global__ void split_bf16(const float* __restrict__ src,
                           __nv_bfloat16* __restrict__ hi,
                           __nv_bfloat16* __restrict__ lo, int n4)
{
    int i = blockIdx.x * blockDim.x + threadIdx.x;
    if (i >= n4) return;
    float4 v = ((const float4*)src)[i];
    __nv_bfloat16 h0 = __float2bfloat16_rn(v.x);
    __nv_bfloat16 h1 = __float2bfloat16_rn(v.y);
    __nv_bfloat16 h2 = __float2bfloat16_rn(v.z);
    __nv_bfloat16 h3 = __float2bfloat16_rn(v.w);
    __nv_bfloat16 l0 = __float2bfloat16_rn(v.x - __bfloat162float(h0));
    __nv_bfloat16 l1 = __float2bfloat16_rn(v.y - __bfloat162float(h1));
    __nv_bfloat16 l2 = __float2bfloat16_rn(v.z - __bfloat162float(h2));
    __nv_bfloat16 l3 = __float2bfloat16_rn(v.w - __bfloat162float(h3));
    __nv_bfloat162* H = (__nv_bfloat162*)hi;
    __nv_bfloat162* L = (__nv_bfloat162*)lo;
    H[2 * i]     = __nv_bfloat162(h0, h1);
    H[2 * i + 1] = __nv_bfloat162(h2, h3);
    L[2 * i]     = __nv_bfloat162(l0, l1);
    L[2 * i + 1] = __nv_bfloat162(l2, l3);
}

// ---------------------------------------------------------------------------
// HMMA QKV GEMM: C = A @ W^T + bias with bf16 2-way split (3 MMA terms).
// CTA tile 128x128, BK=32, 8 warps (2m x 4n), warp tile 64x32.
// smem rows padded to 40 bf16 (80B): conflict-free ldmatrix.
// Grid: x = 18 (3 mats x 6 N-tiles, fastest => L2 A-reuse), y = 512 M-tiles.
// ---------------------------------------------------------------------------
#define BM 128
#define BN 128
#define BK 32
#define NCHUNK (GK / BK)                 // 24
#define ROWB 80                          // padded row bytes (40 bf16)
#define TILE_B (128 * ROWB)              // 10240 B per tile
#define STAGE_B (4 * TILE_B)             // Ah | Al | Bh | Bl = 40960 B
#define GEMM_SMEM (2 * STAGE_B)          // 81920 B

__device__ __forceinline__ void load_chunk(uint32_t st,
                                           const __nv_bfloat16* Ah, const __nv_bfloat16* Al,
                                           const __nv_bfloat16* Bh, const __nv_bfloat16* Bl,
                                           int bm, int bn, int k0, int tid)
{
#pragma unroll
    for (int t = 0; t < 2; ++t) {
        int s   = tid + t * 256;         // 0..511
        int r   = s >> 2;                // row 0..127
        int seg = (s & 3) * 8;           // element offset (8 bf16 = 16B)
        uint32_t soff = (uint32_t)(r * ROWB + seg * 2);
        cp_async16(st + soff,              Ah + (size_t)(bm + r) * GK + k0 + seg);
        cp_async16(st + TILE_B + soff,     Al + (size_t)(bm + r) * GK + k0 + seg);
        cp_async16(st + 2 * TILE_B + soff, Bh + (size_t)(bn + r) * GK + k0 + seg);
        cp_async16(st + 3 * TILE_B + soff, Bl + (size_t)(bn + r) * GK + k0 + seg);
    }
}

__global__ __launch_bounds__(256, 2)
void gemm_hmma(const float* __restrict__ bq, const float* __restrict__ bk,
               const float* __restrict__ bv)
{
    extern __shared__ __align__(128) char smem[];
    const int tid  = threadIdx.x;
    const int wid  = tid >> 5;
    const int lane = tid & 31;
    const int sel  = blockIdx.x / 6;
    const int nt6  = blockIdx.x % 6;
    const int bm   = blockIdx.y * BM;
    const int bn   = nt6 * BN;
    const int wm   = wid >> 2;           // 0-1
    const int wn   = wid & 3;            // 0-3

    const __nv_bfloat16* __restrict__ Ah = g_Xhi;
    const __nv_bfloat16* __restrict__ Al = g_Xlo;
    const __nv_bfloat16* __restrict__ Bh = g_Whi[sel];
    const __nv_bfloat16* __restrict__ Bl = g_Wlo[sel];
    float* __restrict__ C = (sel == 0) ? g_Q : (sel == 1) ? g_K : g_V;
    const float* __restrict__ bias = (sel == 0) ? bq : (sel == 1) ? bk : bv;

    const uint32_t sb = smem_u32(smem);

    float acc[4][4][4];
#pragma unroll
    for (int i = 0; i < 4; i++)
#pragma unroll
        for (int j = 0; j < 4; j++)
#pragma unroll
            for (int u = 0; u < 4; u++) acc[i][j][u] = 0.f;

    // Preload chunks 0, 1
    load_chunk(sb, Ah, Al, Bh, Bl, bm, bn, 0, tid);
    CP_COMMIT();
    load_chunk(sb + STAGE_B, Ah, Al, Bh, Bl, bm, bn, BK, tid);
    CP_COMMIT();

    // Precompute lane-dependent ldmatrix offsets (in bytes)
    const uint32_t a_row = (uint32_t)(wm * 64 + (lane & 15));
    const uint32_t a_koff = (uint32_t)((lane >> 4) << 3);
    const uint32_t b_row = (uint32_t)(wn * 32 + (lane & 7));
    const uint32_t b_koff = (uint32_t)(((lane >> 3) & 1) << 3);

    for (int c = 0; c < NCHUNK; ++c) {
        CP_WAIT1();
        __syncthreads();
        const uint32_t st = sb + (uint32_t)(c & 1) * STAGE_B;

#pragma unroll
        for (int ks = 0; ks < 2; ++ks) {
            const uint32_t k0 = ks * 16;
            uint32_t ah[4][4], al[4][4], bh[4][2], bl[4][2];
#pragma unroll
            for (int mt = 0; mt < 4; ++mt) {
                uint32_t off = ((a_row + mt * 16) * 40 + k0 + a_koff) * 2;
                ldsm_x4(ah[mt], st + off);
                ldsm_x4(al[mt], st + TILE_B + off);
            }
#pragma unroll
            for (int nt = 0; nt < 4; ++nt) {
                uint32_t off = ((b_row + nt * 8) * 40 + k0 + b_koff) * 2;
                ldsm_x2(bh[nt], st + 2 * TILE_B + off);
                ldsm_x2(bl[nt], st + 3 * TILE_B + off);
            }
#pragma unroll
            for (int mt = 0; mt < 4; ++mt)
#pragma unroll
                for (int nt = 0; nt < 4; ++nt) {
                    mma16816(acc[mt][nt], ah[mt], bh[nt]);
                    mma16816(acc[mt][nt], ah[mt], bl[nt]);
                    mma16816(acc[mt][nt], al[mt], bh[nt]);
                }
        }

        __syncthreads();
        if (c + 2 < NCHUNK)
            load_chunk(sb + (uint32_t)(c & 1) * STAGE_B,
                       Ah, Al, Bh, Bl, bm, bn, (c + 2) * BK, tid);
        CP_COMMIT();   // uniform group accounting (possibly empty)
    }

    // Epilogue: fragment -> global with bias
#pragma unroll
    for (int nt = 0; nt < 4; ++nt) {
        const int col = bn + wn * 32 + nt * 8 + (lane & 3) * 2;
        const float2 bb = *(const float2*)(bias + col);
#pragma unroll
        for (int mt = 0; mt < 4; ++mt) {
            const int row = bm + wm * 64 + mt * 16 + (lane >> 2);
            float2 o0, o1;
            o0.x = acc[mt][nt][0] + bb.x;
            o0.y = acc[mt][nt][1] + bb.y;
            o1.x = acc[mt][nt][2] + bb.x;
            o1.y = acc[mt][nt][3] + bb.y;
            *(float2*)(C + (size_t)row * GN + col) = o0;
            *(float2*)(C + (size_t)(row + 8) * GN + col) = o1;
        }
    }
}

// ---------------------------------------------------------------------------
// Fused causal flash attention (unchanged from R1: 819us, fma-bound)
// ---------------------------------------------------------------------------
__global__ __launch_bounds__(256)
void flash_attn(float* __restrict__ O)
{
    extern __shared__ float sm[];
    float* Qs = sm;
    float* Ks = sm + 64 * 68;
    float* Vs = sm + 2 * 64 * 68;
    float* Ps = sm + 3 * 64 * 68;

    const int tid = threadIdx.x;
    const int qt  = blockIdx.x;
    const int h   = blockIdx.y;
    const int g   = blockIdx.z;
    const int tx  = tid & 15;
    const int ty  = tid >> 4;
    const int qy  = ty * 4;
    const int colh = h * 64;
    const size_t qrow0 = (size_t)g * 256 + qt * 64;

#pragma unroll
    for (int t = 0; t < 4; t++) {
        int f4 = tid + t * 256;
        int r  = f4 >> 4;
        int c  = (f4 & 15) * 4;
        *(float4*)(Qs + r * 68 + c) =
            *(const float4*)(g_Q + (qrow0 + r) * 768 + colh + c);
    }

    float m_i[4], l_i[4], acc[4][4];
#pragma unroll
    for (int i = 0; i < 4; i++) {
        m_i[i] = -1e30f;
        l_i[i] = 0.f;
#pragma unroll
        for (int j = 0; j < 4; j++) acc[i][j] = 0.f;
    }

    for (int kt = 0; kt <= qt; kt++) {
        __syncthreads();
        const size_t krow0 = (size_t)g * 256 + kt * 64;
#pragma unroll
        for (int t = 0; t < 4; t++) {
            int f4 = tid + t * 256;
            int r  = f4 >> 4;
            int c  = (f4 & 15) * 4;
            *(float4*)(Ks + r * 68 + c) =
                *(const float4*)(g_K + (krow0 + r) * 768 + colh + c);
            *(float4*)(Vs + r * 68 + c) =
                *(const float4*)(g_V + (krow0 + r) * 768 + colh + c);
        }
        __syncthreads();

        float s[4][4];
#pragma unroll
        for (int i = 0; i < 4; i++)
#pragma unroll
            for (int j = 0; j < 4; j++) s[i][j] = 0.f;

#pragma unroll
        for (int dd = 0; dd < 64; dd += 4) {
            float4 qv[4], kv[4];
#pragma unroll
            for (int i = 0; i < 4; i++)
                qv[i] = *(const float4*)(Qs + (qy + i) * 68 + dd);
#pragma unroll
            for (int j = 0; j < 4; j++)
                kv[j] = *(const float4*)(Ks + (tx + 16 * j) * 68 + dd);
#pragma unroll
            for (int i = 0; i < 4; i++) {
                const float* qf = (const float*)&qv[i];
#pragma unroll
                for (int j = 0; j < 4; j++) {
                    const float* kf = (const float*)&kv[j];
#pragma unroll
                    for (int u = 0; u < 4; u++)
                        s[i][j] = fmaf(qf[u], kf[u], s[i][j]);
                }
            }
        }

        const float scale = 0.125f;
#pragma unroll
        for (int i = 0; i < 4; i++)
#pragma unroll
            for (int j = 0; j < 4; j++) {
                s[i][j] *= scale;
                if (kt == qt && (tx + 16 * j) > (qy + i)) s[i][j] = -1e30f;
            }

        float mt[4];
#pragma unroll
        for (int i = 0; i < 4; i++)
            mt[i] = fmaxf(fmaxf(s[i][0], s[i][1]), fmaxf(s[i][2], s[i][3]));
#pragma unroll
        for (int off = 8; off >= 1; off >>= 1)
#pragma unroll
            for (int i = 0; i < 4; i++)
                mt[i] = fmaxf(mt[i], __shfl_xor_sync(0xffffffffu, mt[i], off));

        float p[4][4], rs[4];
#pragma unroll
        for (int i = 0; i < 4; i++) {
            float mnew = fmaxf(m_i[i], mt[i]);
            float corr = __expf(m_i[i] - mnew);
            m_i[i] = mnew;
            float r0 = 0.f;
#pragma unroll
            for (int j = 0; j < 4; j++) {
                p[i][j] = __expf(s[i][j] - mnew);
                r0 += p[i][j];
            }
            rs[i] = r0;
            l_i[i] *= corr;
#pragma unroll
            for (int j = 0; j < 4; j++) acc[i][j] *= corr;
        }
#pragma unroll
        for (int off = 8; off >= 1; off >>= 1)
#pragma unroll
            for (int i = 0; i < 4; i++)
                rs[i] += __shfl_xor_sync(0xffffffffu, rs[i], off);
#pragma unroll
        for (int i = 0; i < 4; i++) l_i[i] += rs[i];

#pragma unroll
        for (int i = 0; i < 4; i++)
#pragma unroll
            for (int j = 0; j < 4; j++)
                Ps[(qy + i) * 68 + tx + 16 * j] = p[i][j];
        __syncthreads();

#pragma unroll
        for (int kk = 0; kk < 64; kk += 4) {
            float4 pv[4], vv[4];
#pragma unroll
            for (int i = 0; i < 4; i++)
                pv[i] = *(const float4*)(Ps + (qy + i) * 68 + kk);
#pragma unroll
            for (int t = 0; t < 4; t++)
                vv[t] = *(const float4*)(Vs + (kk + t) * 68 + tx * 4);
#pragma unroll
            for (int i = 0; i < 4; i++) {
                const float* pf = (const float*)&pv[i];
#pragma unroll
                for (int t = 0; t < 4; t++) {
                    const float* vt = (const float*)&vv[t];
#pragma unroll
                    for (int j = 0; j < 4; j++)
                        acc[i][j] = fmaf(pf[t], vt[j], acc[i][j]);
                }
            }
        }
    }

#pragma unroll
    for (int i = 0; i < 4; i++) {
        float inv = 1.0f / l_i[i];
        float4 o;
        o.x = acc[i][0] * inv;
        o.y = acc[i][1] * inv;
        o.z = acc[i][2] * inv;
        o.w = acc[i][3] * inv;
        *(float4*)(O + (qrow0 + qy + i) * 768 + colh + tx * 4) = o;
    }
}

// ---------------------------------------------------------------------------
extern "C" void kernel_launch(void* const* d_in, const int* in_sizes, int n_in,
                              void* d_out, int out_size)
{
    const float* X  = (const float*)d_in[0];
    const float* Wq = (const float*)d_in[1];
    const float* bq = (const float*)d_in[2];
    const float* Wk = (const float*)d_in[3];
    const float* bk = (const float*)d_in[4];
    const float* Wv = (const float*)d_in[5];
    const float* bv = (const float*)d_in[6];
    float* O = (float*)d_out;

    __nv_bfloat16 *xhi, *xlo, *whi, *wlo;
    cudaGetSymbolAddress((void**)&xhi, g_Xhi);
    cudaGetSymbolAddress((void**)&xlo, g_Xlo);
    cudaGetSymbolAddress((void**)&whi, g_Whi);
    cudaGetSymbolAddress((void**)&wlo, g_Wlo);

    {
        int n4 = (GM * GK) / 4;
        split_bf16<<<(n4 + 255) / 256, 256>>>(X, xhi, xlo, n4);
        int w4 = (GN * GK) / 4;
        split_bf16<<<(w4 + 255) / 256, 256>>>(Wq, whi + 0 * (size_t)GN * GK,
                                              wlo + 0 * (size_t)GN * GK, w4);
        split_bf16<<<(w4 + 255) / 256, 256>>>(Wk, whi + 1 * (size_t)GN * GK,
                                              wlo + 1 * (size_t)GN * GK, w4);
        split_bf16<<<(w4 + 255) / 256, 256>>>(Wv, whi + 2 * (size_t)GN * GK,
                                              wlo + 2 * (size_t)GN * GK, w4);
    }

    cudaFuncSetAttribute(gemm_hmma, cudaFuncAttributeMaxDynamicSharedMemorySize, GEMM_SMEM);
    dim3 ggrid(18, GM / BM);
    gemm_hmma<<<ggrid, 256, GEMM_SMEM>>>(bq, bk, bv);

    const int attn_smem = 4 * 64 * 68 * (int)sizeof(float);
    cudaFuncSetAttribute(flash_attn, cudaFuncAttributeMaxDynamicSharedMemorySize, attn_smem);
    dim3 agrid(4, 12, 256);
    flash_attn<<<agrid, 256, attn_smem>>>(O);
}

// round 7
// speedup vs baseline: 2.5622x; 1.1789x over previous
#include <cuda_runtime.h>
#include <cuda_bf16.h>
#include <cstdint>
#include <math.h>

#define GM 65536
#define GK 768
#define GN 768

// ---------------------------------------------------------------------------
// Device scratch (allocation-free rule: __device__ globals)
// Q/K/V are stored as bf16 hi/lo split pairs (same bytes as fp32).
// ---------------------------------------------------------------------------
__device__ __nv_bfloat16 g_Qh[(size_t)GM * GN];
__device__ __nv_bfloat16 g_Ql[(size_t)GM * GN];
__device__ __nv_bfloat16 g_Kh[(size_t)GM * GN];
__device__ __nv_bfloat16 g_Kl[(size_t)GM * GN];
__device__ __nv_bfloat16 g_Vh[(size_t)GM * GN];
__device__ __nv_bfloat16 g_Vl[(size_t)GM * GN];
__device__ __nv_bfloat16 g_Xhi[(size_t)GM * GK];
__device__ __nv_bfloat16 g_Xlo[(size_t)GM * GK];
__device__ __nv_bfloat16 g_Whi[3][(size_t)GN * GK];
__device__ __nv_bfloat16 g_Wlo[3][(size_t)GN * GK];

// ---------------------------------------------------------------------------
// Baseline-ISA helpers (compute_103-safe: no tcgen05 / TMEM)
// ---------------------------------------------------------------------------
__device__ __forceinline__ uint32_t smem_u32(const void* p) {
    uint32_t a;
    asm("{ .reg .u64 t; cvta.to.shared.u64 t, %1; cvt.u32.u64 %0, t; }"
        : "=r"(a) : "l"(p));
    return a;
}

__device__ __forceinline__ void cp_async16(uint32_t saddr, const void* gptr) {
    asm volatile("cp.async.cg.shared.global [%0], [%1], 16;"
                 :: "r"(saddr), "l"(gptr) : "memory");
}
#define CP_COMMIT() asm volatile("cp.async.commit_group;" ::: "memory")
#define CP_WAIT1()  asm volatile("cp.async.wait_group 1;" ::: "memory")

__device__ __forceinline__ void ldsm_x4(uint32_t* r, uint32_t addr) {
    asm volatile("ldmatrix.sync.aligned.m8n8.x4.shared.b16 {%0,%1,%2,%3}, [%4];"
                 : "=r"(r[0]), "=r"(r[1]), "=r"(r[2]), "=r"(r[3]) : "r"(addr));
}
__device__ __forceinline__ void ldsm_x4_t(uint32_t* r, uint32_t addr) {
    asm volatile("ldmatrix.sync.aligned.m8n8.x4.trans.shared.b16 {%0,%1,%2,%3}, [%4];"
                 : "=r"(r[0]), "=r"(r[1]), "=r"(r[2]), "=r"(r[3]) : "r"(addr));
}
__device__ __forceinline__ void ldsm_x2(uint32_t* r, uint32_t addr) {
    asm volatile("ldmatrix.sync.aligned.m8n8.x2.shared.b16 {%0,%1}, [%2];"
                 : "=r"(r[0]), "=r"(r[1]) : "r"(addr));
}
__device__ __forceinline__ void mma16816(float* c, const uint32_t* a, const uint32_t* b) {
    asm volatile(
        "mma.sync.aligned.m16n8k16.row.col.f32.bf16.bf16.f32 "
        "{%0,%1,%2,%3}, {%4,%5,%6,%7}, {%8,%9}, {%0,%1,%2,%3};"
        : "+f"(c[0]), "+f"(c[1]), "+f"(c[2]), "+f"(c[3])
        : "r"(a[0]), "r"(a[1]), "r"(a[2]), "r"(a[3]), "r"(b[0]), "r"(b[1]));
}
// pack two f32 into bf16x2: lo -> bits[15:0], hi -> bits[31:16]
__device__ __forceinline__ uint32_t pack_bf16(float lo, float hi) {
    uint32_t d;
    asm("cvt.rn.bf16x2.f32 %0, %1, %2;" : "=r"(d) : "f"(hi), "f"(lo));
    return d;
}
__device__ __forceinline__ float bf16_round(float x) {
    return __bfloat162float(__float2bfloat16_rn(x));
}

// ---------------------------------------------------------------------------
// Split conversion: x -> bf16 hi + bf16 lo
// ---------------------------------------------------------------------------
__global__ void split_bf16(const float* __restrict__ src,
                           __nv_bfloat16* __restrict__ hi,
                           __nv_bfloat16* __restrict__ lo, int n4)
{
    int i = blockIdx.x * blockDim.x + threadIdx.x;
    if (i >= n4) return;
    float4 v = ((const float4*)src)[i];
    uint32_t* H = (uint32_t*)hi;
    uint32_t* L = (uint32_t*)lo;
    H[2 * i]     = pack_bf16(v.x, v.y);
    H[2 * i + 1] = pack_bf16(v.z, v.w);
    L[2 * i]     = pack_bf16(v.x - bf16_round(v.x), v.y - bf16_round(v.y));
    L[2 * i + 1] = pack_bf16(v.z - bf16_round(v.z), v.w - bf16_round(v.w));
}

// ---------------------------------------------------------------------------
// HMMA QKV GEMM: C = A @ W^T + bias with bf16 2-way split (3 MMA terms).
// CTA tile 128x128, BK=32, 8 warps (2m x 4n), warp tile 64x32.
// Epilogue emits bf16 hi/lo split pairs for the attention stage.
// ---------------------------------------------------------------------------
#define BM 128
#define BN 128
#define BK 32
#define NCHUNK (GK / BK)                 // 24
#define ROWB 80                          // padded row bytes (40 bf16)
#define TILE_B (128 * ROWB)              // 10240 B per tile
#define STAGE_B (4 * TILE_B)             // Ah | Al | Bh | Bl = 40960 B
#define GEMM_SMEM (2 * STAGE_B)          // 81920 B

__device__ __forceinline__ void load_chunk(uint32_t st,
                                           const __nv_bfloat16* Ah, const __nv_bfloat16* Al,
                                           const __nv_bfloat16* Bh, const __nv_bfloat16* Bl,
                                           int bm, int bn, int k0, int tid)
{
#pragma unroll
    for (int t = 0; t < 2; ++t) {
        int s   = tid + t * 256;         // 0..511
        int r   = s >> 2;                // row 0..127
        int seg = (s & 3) * 8;           // element offset (8 bf16 = 16B)
        uint32_t soff = (uint32_t)(r * ROWB + seg * 2);
        cp_async16(st + soff,              Ah + (size_t)(bm + r) * GK + k0 + seg);
        cp_async16(st + TILE_B + soff,     Al + (size_t)(bm + r) * GK + k0 + seg);
        cp_async16(st + 2 * TILE_B + soff, Bh + (size_t)(bn + r) * GK + k0 + seg);
        cp_async16(st + 3 * TILE_B + soff, Bl + (size_t)(bn + r) * GK + k0 + seg);
    }
}

__global__ __launch_bounds__(256, 2)
void gemm_hmma(const float* __restrict__ bq, const float* __restrict__ bk,
               const float* __restrict__ bv)
{
    extern __shared__ __align__(128) char smem[];
    const int tid  = threadIdx.x;
    const int wid  = tid >> 5;
    const int lane = tid & 31;
    const int sel  = blockIdx.x / 6;
    const int nt6  = blockIdx.x % 6;
    const int bm   = blockIdx.y * BM;
    const int bn   = nt6 * BN;
    const int wm   = wid >> 2;           // 0-1
    const int wn   = wid & 3;            // 0-3

    const __nv_bfloat16* __restrict__ Ah = g_Xhi;
    const __nv_bfloat16* __restrict__ Al = g_Xlo;
    const __nv_bfloat16* __restrict__ Bh = g_Whi[sel];
    const __nv_bfloat16* __restrict__ Bl = g_Wlo[sel];
    __nv_bfloat16* __restrict__ Ch = (sel == 0) ? g_Qh : (sel == 1) ? g_Kh : g_Vh;
    __nv_bfloat16* __restrict__ Cl = (sel == 0) ? g_Ql : (sel == 1) ? g_Kl : g_Vl;
    const float* __restrict__ bias = (sel == 0) ? bq : (sel == 1) ? bk : bv;

    const uint32_t sb = smem_u32(smem);

    float acc[4][4][4];
#pragma unroll
    for (int i = 0; i < 4; i++)
#pragma unroll
        for (int j = 0; j < 4; j++)
#pragma unroll
            for (int u = 0; u < 4; u++) acc[i][j][u] = 0.f;

    load_chunk(sb, Ah, Al, Bh, Bl, bm, bn, 0, tid);
    CP_COMMIT();
    load_chunk(sb + STAGE_B, Ah, Al, Bh, Bl, bm, bn, BK, tid);
    CP_COMMIT();

    const uint32_t a_row = (uint32_t)(wm * 64 + (lane & 15));
    const uint32_t a_koff = (uint32_t)((lane >> 4) << 3);
    const uint32_t b_row = (uint32_t)(wn * 32 + (lane & 7));
    const uint32_t b_koff = (uint32_t)(((lane >> 3) & 1) << 3);

    for (int c = 0; c < NCHUNK; ++c) {
        CP_WAIT1();
        __syncthreads();
        const uint32_t st = sb + (uint32_t)(c & 1) * STAGE_B;

#pragma unroll
        for (int ks = 0; ks < 2; ++ks) {
            const uint32_t k0 = ks * 16;
            uint32_t ah[4][4], al[4][4], bh[4][2], bl[4][2];
#pragma unroll
            for (int mt = 0; mt < 4; ++mt) {
                uint32_t off = ((a_row + mt * 16) * 40 + k0 + a_koff) * 2;
                ldsm_x4(ah[mt], st + off);
                ldsm_x4(al[mt], st + TILE_B + off);
            }
#pragma unroll
            for (int nt = 0; nt < 4; ++nt) {
                uint32_t off = ((b_row + nt * 8) * 40 + k0 + b_koff) * 2;
                ldsm_x2(bh[nt], st + 2 * TILE_B + off);
                ldsm_x2(bl[nt], st + 3 * TILE_B + off);
            }
#pragma unroll
            for (int mt = 0; mt < 4; ++mt)
#pragma unroll
                for (int nt = 0; nt < 4; ++nt) {
                    mma16816(acc[mt][nt], ah[mt], bh[nt]);
                    mma16816(acc[mt][nt], ah[mt], bl[nt]);
                    mma16816(acc[mt][nt], al[mt], bh[nt]);
                }
        }

        __syncthreads();
        if (c + 2 < NCHUNK)
            load_chunk(sb + (uint32_t)(c & 1) * STAGE_B,
                       Ah, Al, Bh, Bl, bm, bn, (c + 2) * BK, tid);
        CP_COMMIT();
    }

    // Epilogue: bias add, bf16 hi/lo split store
#pragma unroll
    for (int nt = 0; nt < 4; ++nt) {
        const int col = bn + wn * 32 + nt * 8 + (lane & 3) * 2;
        const float2 bb = *(const float2*)(bias + col);
#pragma unroll
        for (int mt = 0; mt < 4; ++mt) {
            const int row = bm + wm * 64 + mt * 16 + (lane >> 2);
            float v0 = acc[mt][nt][0] + bb.x;
            float v1 = acc[mt][nt][1] + bb.y;
            float v2 = acc[mt][nt][2] + bb.x;
            float v3 = acc[mt][nt][3] + bb.y;
            size_t i0 = (size_t)row * GN + col;
            size_t i1 = (size_t)(row + 8) * GN + col;
            *(uint32_t*)(Ch + i0) = pack_bf16(v0, v1);
            *(uint32_t*)(Cl + i0) = pack_bf16(v0 - bf16_round(v0), v1 - bf16_round(v1));
            *(uint32_t*)(Ch + i1) = pack_bf16(v2, v3);
            *(uint32_t*)(Cl + i1) = pack_bf16(v2 - bf16_round(v2), v3 - bf16_round(v3));
        }
    }
}

// ---------------------------------------------------------------------------
// HMMA fused causal flash attention.
// Grid (qt=4, h=12, g=256), 128 threads = 4 warps; warp owns 16 q rows.
// K [key][d] -> B frags via ldmatrix; V via ldmatrix.trans.
// S = Qh.Kh + Qh.Kl + Ql.Kh;  O += Ph.Vh + Pl.Vh + Ph.Vl  (P split in regs).
// smem rows padded to 72 bf16 (144B) -> conflict-free ldmatrix.
// ---------------------------------------------------------------------------
#define FSTR 72
#define FTILE_B (64 * FSTR * 2)          // 9216 B per 64x64 bf16 tile
#define FQ_B (2 * FTILE_B)               // Qh | Ql
#define FSTAGE_B (4 * FTILE_B)           // Kh | Kl | Vh | Vl = 36864 B
#define FLASH_SMEM (FQ_B + 2 * FSTAGE_B) // 92160 B

__device__ __forceinline__ void flash_load_tile(uint32_t base, size_t krow0,
                                                int colh, int tid)
{
#pragma unroll
    for (int i = 0; i < 4; ++i) {
        int id  = tid + i * 128;         // 0..511
        int r   = id >> 3;               // row 0..63
        int seg = (id & 7) * 16;         // byte offset in 128B row
        uint32_t soff = (uint32_t)(r * 144 + seg);
        const char* gk = (const char*)(g_Kh + (krow0 + r) * GN + colh) + seg;
        const char* gl = (const char*)(g_Kl + (krow0 + r) * GN + colh) + seg;
        const char* gv = (const char*)(g_Vh + (krow0 + r) * GN + colh) + seg;
        const char* gw = (const char*)(g_Vl + (krow0 + r) * GN + colh) + seg;
        cp_async16(base + soff, gk);
        cp_async16(base + FTILE_B + soff, gl);
        cp_async16(base + 2 * FTILE_B + soff, gv);
        cp_async16(base + 3 * FTILE_B + soff, gw);
    }
}

__global__ __launch_bounds__(128)
void flash_attn_tc(float* __restrict__ O)
{
    extern __shared__ __align__(128) char smem[];
    const int tid  = threadIdx.x;
    const int warp = tid >> 5;
    const int lane = tid & 31;
    const int qt   = blockIdx.x;
    const int h    = blockIdx.y;
    const int g    = blockIdx.z;
    const int colh = h * 64;
    const size_t qrow0 = (size_t)g * 256 + qt * 64;
    const uint32_t sb = smem_u32(smem);

    // Load Q hi/lo (group with tile 0)
#pragma unroll
    for (int i = 0; i < 4; ++i) {
        int id  = tid + i * 128;
        int r   = id >> 3;
        int seg = (id & 7) * 16;
        uint32_t soff = (uint32_t)(r * 144 + seg);
        cp_async16(sb + soff, (const char*)(g_Qh + (qrow0 + r) * GN + colh) + seg);
        cp_async16(sb + FTILE_B + soff, (const char*)(g_Ql + (qrow0 + r) * GN + colh) + seg);
    }
    flash_load_tile(sb + FQ_B, (size_t)g * 256, colh, tid);
    CP_COMMIT();
    if (qt > 0) flash_load_tile(sb + FQ_B + FSTAGE_B, (size_t)g * 256 + 64, colh, tid);
    CP_COMMIT();

    const int lm = lane >> 3;            // ldmatrix matrix id
    const int lr = lane & 7;             // row within matrix
    const int r0 = warp * 16;
    // A-frag addressing (Q, P): m0 rows-lo/k-lo, m1 rows-hi/k-lo, m2 lo/hi, m3 hi/hi
    const uint32_t a_off0 = (uint32_t)(((r0 + (lm & 1) * 8 + lr) * FSTR + (lm >> 1) * 8) * 2);
    // B-frag addressing (K, non-trans): n(key)=(lm>>1)*8 + lr, k(d)=(lm&1)*8
    const uint32_t kb_off0 = (uint32_t)((((lm >> 1) * 8 + lr) * FSTR + (lm & 1) * 8) * 2);
    // B-frag addressing (V, trans): k(key)=(lm&1)*8 + lr, n(d)=(lm>>1)*8
    const uint32_t vb_off0 = (uint32_t)((((lm & 1) * 8 + lr) * FSTR + (lm >> 1) * 8) * 2);

    uint32_t qh[4][4];
    float m_[2] = {-1e30f, -1e30f};
    float l_[2] = {0.f, 0.f};
    float o[8][4];
#pragma unroll
    for (int j = 0; j < 8; ++j)
#pragma unroll
        for (int c = 0; c < 4; ++c) o[j][c] = 0.f;

    const int ra = warp * 16 + (lane >> 2);   // local q row (half A)
    const int rb = ra + 8;                    // half B

    for (int kt = 0; kt <= qt; ++kt) {
        CP_WAIT1();
        __syncthreads();
        const uint32_t kb = sb + FQ_B + (uint32_t)(kt & 1) * FSTAGE_B;

        if (kt == 0) {
#pragma unroll
            for (int kc = 0; kc < 4; ++kc)
                ldsm_x4(qh[kc], sb + a_off0 + kc * 32);
        }

        // ---- S = scale * (Qh.Kh + Qh.Kl + Ql.Kh) ----
        float s[8][4];
#pragma unroll
        for (int j = 0; j < 8; ++j)
#pragma unroll
            for (int c = 0; c < 4; ++c) s[j][c] = 0.f;

#pragma unroll
        for (int kc = 0; kc < 4; ++kc) {
            uint32_t qlf[4];
            ldsm_x4(qlf, sb + FTILE_B + a_off0 + kc * 32);
#pragma unroll
            for (int p = 0; p < 4; ++p) {
                uint32_t kh4[4], kl4[4];
                uint32_t off = kb_off0 + (uint32_t)((p * 16 * FSTR + kc * 16) * 2);
                ldsm_x4(kh4, kb + off);
                ldsm_x4(kl4, kb + FTILE_B + off);
                mma16816(s[2 * p],     qh[kc], kh4);
                mma16816(s[2 * p],     qh[kc], kl4);
                mma16816(s[2 * p],     qlf,    kh4);
                mma16816(s[2 * p + 1], qh[kc], kh4 + 2);
                mma16816(s[2 * p + 1], qh[kc], kl4 + 2);
                mma16816(s[2 * p + 1], qlf,    kh4 + 2);
            }
        }

        // ---- scale + causal mask ----
        const float scale = 0.125f;
#pragma unroll
        for (int j = 0; j < 8; ++j)
#pragma unroll
            for (int c = 0; c < 4; ++c) s[j][c] *= scale;
        if (kt == qt) {
#pragma unroll
            for (int j = 0; j < 8; ++j) {
                int k0j = j * 8 + (lane & 3) * 2;
                if (k0j     > ra) s[j][0] = -1e30f;
                if (k0j + 1 > ra) s[j][1] = -1e30f;
                if (k0j     > rb) s[j][2] = -1e30f;
                if (k0j + 1 > rb) s[j][3] = -1e30f;
            }
        }

        // ---- online softmax ----
        float mA = -1e30f, mB = -1e30f;
#pragma unroll
        for (int j = 0; j < 8; ++j) {
            mA = fmaxf(mA, fmaxf(s[j][0], s[j][1]));
            mB = fmaxf(mB, fmaxf(s[j][2], s[j][3]));
        }
        mA = fmaxf(mA, __shfl_xor_sync(0xffffffffu, mA, 1));
        mA = fmaxf(mA, __shfl_xor_sync(0xffffffffu, mA, 2));
        mB = fmaxf(mB, __shfl_xor_sync(0xffffffffu, mB, 1));
        mB = fmaxf(mB, __shfl_xor_sync(0xffffffffu, mB, 2));

        float mnA = fmaxf(m_[0], mA), mnB = fmaxf(m_[1], mB);
        float corrA = __expf(m_[0] - mnA), corrB = __expf(m_[1] - mnB);
        m_[0] = mnA; m_[1] = mnB;

        float rsA = 0.f, rsB = 0.f;
#pragma unroll
        for (int j = 0; j < 8; ++j) {
            s[j][0] = __expf(s[j][0] - mnA);
            s[j][1] = __expf(s[j][1] - mnA);
            s[j][2] = __expf(s[j][2] - mnB);
            s[j][3] = __expf(s[j][3] - mnB);
            rsA += s[j][0] + s[j][1];
            rsB += s[j][2] + s[j][3];
        }
        rsA += __shfl_xor_sync(0xffffffffu, rsA, 1);
        rsA += __shfl_xor_sync(0xffffffffu, rsA, 2);
        rsB += __shfl_xor_sync(0xffffffffu, rsB, 1);
        rsB += __shfl_xor_sync(0xffffffffu, rsB, 2);
        l_[0] = l_[0] * corrA + rsA;
        l_[1] = l_[1] * corrB + rsB;

#pragma unroll
        for (int j = 0; j < 8; ++j) {
            o[j][0] *= corrA; o[j][1] *= corrA;
            o[j][2] *= corrB; o[j][3] *= corrB;
        }

        // ---- pack P -> bf16 hi/lo A-frags ----
        uint32_t ph[4][4], pl[4][4];
#pragma unroll
        for (int kc = 0; kc < 4; ++kc) {
            int j0 = 2 * kc, j1 = j0 + 1;
            ph[kc][0] = pack_bf16(s[j0][0], s[j0][1]);
            ph[kc][1] = pack_bf16(s[j0][2], s[j0][3]);
            ph[kc][2] = pack_bf16(s[j1][0], s[j1][1]);
            ph[kc][3] = pack_bf16(s[j1][2], s[j1][3]);
            pl[kc][0] = pack_bf16(s[j0][0] - bf16_round(s[j0][0]),
                                  s[j0][1] - bf16_round(s[j0][1]));
            pl[kc][1] = pack_bf16(s[j0][2] - bf16_round(s[j0][2]),
                                  s[j0][3] - bf16_round(s[j0][3]));
            pl[kc][2] = pack_bf16(s[j1][0] - bf16_round(s[j1][0]),
                                  s[j1][1] - bf16_round(s[j1][1]));
            pl[kc][3] = pack_bf16(s[j1][2] - bf16_round(s[j1][2]),
                                  s[j1][3] - bf16_round(s[j1][3]));
        }

        // ---- O += Ph.Vh + Pl.Vh + Ph.Vl ----
#pragma unroll
        for (int kc = 0; kc < 4; ++kc) {
#pragma unroll
            for (int p = 0; p < 4; ++p) {
                uint32_t vh4[4], vl4[4];
                uint32_t off = vb_off0 + (uint32_t)((kc * 16 * FSTR + p * 16) * 2);
                ldsm_x4_t(vh4, kb + 2 * FTILE_B + off);
                ldsm_x4_t(vl4, kb + 3 * FTILE_B + off);
                mma16816(o[2 * p],     ph[kc], vh4);
                mma16816(o[2 * p],     pl[kc], vh4);
                mma16816(o[2 * p],     ph[kc], vl4);
                mma16816(o[2 * p + 1], ph[kc], vh4 + 2);
                mma16816(o[2 * p + 1], pl[kc], vh4 + 2);
                mma16816(o[2 * p + 1], ph[kc], vl4 + 2);
            }
        }

        __syncthreads();
        if (kt + 2 <= qt)
            flash_load_tile(sb + FQ_B + (uint32_t)(kt & 1) * FSTAGE_B,
                            (size_t)g * 256 + (kt + 2) * 64, colh, tid);
        CP_COMMIT();
    }

    // ---- epilogue ----
    const float invA = 1.0f / l_[0];
    const float invB = 1.0f / l_[1];
#pragma unroll
    for (int j = 0; j < 8; ++j) {
        const int col = colh + j * 8 + (lane & 3) * 2;
        const size_t rA = qrow0 + warp * 16 + (lane >> 2);
        float2 oa, ob;
        oa.x = o[j][0] * invA; oa.y = o[j][1] * invA;
        ob.x = o[j][2] * invB; ob.y = o[j][3] * invB;
        *(float2*)(O + rA * GN + col) = oa;
        *(float2*)(O + (rA + 8) * GN + col) = ob;
    }
}

// ---------------------------------------------------------------------------
extern "C" void kernel_launch(void* const* d_in, const int* in_sizes, int n_in,
                              void* d_out, int out_size)
{
    const float* X  = (const float*)d_in[0];
    const float* Wq = (const float*)d_in[1];
    const float* bq = (const float*)d_in[2];
    const float* Wk = (const float*)d_in[3];
    const float* bk = (const float*)d_in[4];
    const float* Wv = (const float*)d_in[5];
    const float* bv = (const float*)d_in[6];
    float* O = (float*)d_out;

    __nv_bfloat16 *xhi, *xlo, *whi, *wlo;
    cudaGetSymbolAddress((void**)&xhi, g_Xhi);
    cudaGetSymbolAddress((void**)&xlo, g_Xlo);
    cudaGetSymbolAddress((void**)&whi, g_Whi);
    cudaGetSymbolAddress((void**)&wlo, g_Wlo);

    {
        int n4 = (GM * GK) / 4;
        split_bf16<<<(n4 + 255) / 256, 256>>>(X, xhi, xlo, n4);
        int w4 = (GN * GK) / 4;
        split_bf16<<<(w4 + 255) / 256, 256>>>(Wq, whi + 0 * (size_t)GN * GK,
                                              wlo + 0 * (size_t)GN * GK, w4);
        split_bf16<<<(w4 + 255) / 256, 256>>>(Wk, whi + 1 * (size_t)GN * GK,
                                              wlo + 1 * (size_t)GN * GK, w4);
        split_bf16<<<(w4 + 255) / 256, 256>>>(Wv, whi + 2 * (size_t)GN * GK,
                                              wlo + 2 * (size_t)GN * GK, w4);
    }

    cudaFuncSetAttribute(gemm_hmma, cudaFuncAttributeMaxDynamicSharedMemorySize, GEMM_SMEM);
    dim3 ggrid(18, GM / BM);
    gemm_hmma<<<ggrid, 256, GEMM_SMEM>>>(bq, bk, bv);

    cudaFuncSetAttribute(flash_attn_tc, cudaFuncAttributeMaxDynamicSharedMemorySize, FLASH_SMEM);
    dim3 agrid(4, 12, 256);
    flash_attn_tc<<<agrid, 128, FLASH_SMEM>>>(O);
}

// round 11
// speedup vs baseline: 5.1136x; 1.9958x over previous
#include <cuda_runtime.h>
#include <cuda_fp16.h>
#include <cstdint>
#include <math.h>

#define GM 65536
#define GK 768
#define GN 768

// ---------------------------------------------------------------------------
// Device scratch (allocation-free rule: __device__ globals)
// X/W: single fp16. Q/K/V: fp16 hi/lo split pairs (attention stays exact).
// ---------------------------------------------------------------------------
__device__ __half g_Qh[(size_t)GM * GN];
__device__ __half g_Ql[(size_t)GM * GN];
__device__ __half g_Kh[(size_t)GM * GN];
__device__ __half g_Kl[(size_t)GM * GN];
__device__ __half g_Vh[(size_t)GM * GN];
__device__ __half g_Vl[(size_t)GM * GN];
__device__ __half g_Xh[(size_t)GM * GK];
__device__ __half g_Wh[3][(size_t)GN * GK];

// ---------------------------------------------------------------------------
// Baseline-ISA helpers (compute_103-safe)
// ---------------------------------------------------------------------------
__device__ __forceinline__ uint32_t smem_u32(const void* p) {
    uint32_t a;
    asm("{ .reg .u64 t; cvta.to.shared.u64 t, %1; cvt.u32.u64 %0, t; }"
        : "=r"(a) : "l"(p));
    return a;
}

__device__ __forceinline__ void cp_async16(uint32_t saddr, const void* gptr) {
    asm volatile("cp.async.cg.shared.global [%0], [%1], 16;"
                 :: "r"(saddr), "l"(gptr) : "memory");
}
#define CP_COMMIT() asm volatile("cp.async.commit_group;" ::: "memory")
#define CP_WAIT1()  asm volatile("cp.async.wait_group 1;" ::: "memory")

__device__ __forceinline__ void ldsm_x4(uint32_t* r, uint32_t addr) {
    asm volatile("ldmatrix.sync.aligned.m8n8.x4.shared.b16 {%0,%1,%2,%3}, [%4];"
                 : "=r"(r[0]), "=r"(r[1]), "=r"(r[2]), "=r"(r[3]) : "r"(addr));
}
__device__ __forceinline__ void ldsm_x4_t(uint32_t* r, uint32_t addr) {
    asm volatile("ldmatrix.sync.aligned.m8n8.x4.trans.shared.b16 {%0,%1,%2,%3}, [%4];"
                 : "=r"(r[0]), "=r"(r[1]), "=r"(r[2]), "=r"(r[3]) : "r"(addr));
}
// fp16 HMMA, fp32 accumulate
__device__ __forceinline__ void mma16816(float* c, const uint32_t* a, const uint32_t* b) {
    asm volatile(
        "mma.sync.aligned.m16n8k16.row.col.f32.f16.f16.f32 "
        "{%0,%1,%2,%3}, {%4,%5,%6,%7}, {%8,%9}, {%0,%1,%2,%3};"
        : "+f"(c[0]), "+f"(c[1]), "+f"(c[2]), "+f"(c[3])
        : "r"(a[0]), "r"(a[1]), "r"(a[2]), "r"(a[3]), "r"(b[0]), "r"(b[1]));
}
// pack two f32 into f16x2: lo -> bits[15:0], hi -> bits[31:16]
__device__ __forceinline__ uint32_t pack_f16(float lo, float hi) {
    __half2 h = __floats2half2_rn(lo, hi);
    return *(uint32_t*)&h;
}
__device__ __forceinline__ float f16_round(float x) {
    return __half2float(__float2half_rn(x));
}

// ---------------------------------------------------------------------------
// fp32 -> fp16 convert
// ---------------------------------------------------------------------------
__global__ void to_f16(const float* __restrict__ src, __half* __restrict__ dst, int n4)
{
    int i = blockIdx.x * blockDim.x + threadIdx.x;
    if (i >= n4) return;
    float4 v = ((const float4*)src)[i];
    uint32_t* D = (uint32_t*)dst;
    D[2 * i]     = pack_f16(v.x, v.y);
    D[2 * i + 1] = pack_f16(v.z, v.w);
}

// ---------------------------------------------------------------------------
// fp16 single-term HMMA QKV GEMM: C = A @ W^T + bias.
// CTA 128x128, BK=64, 8 warps (2m x 4n), warp tile 64x32.
// Epilogue emits fp16 hi/lo split pairs for the attention stage.
// smem rows padded to 72 fp16 (144 B) -> conflict-free ldmatrix.
// ---------------------------------------------------------------------------
#define BM 128
#define BN 128
#define BK 64
#define NCHUNK (GK / BK)                 // 12
#define ROWH 72                          // padded row, fp16 elems
#define ROWB 144                         // padded row bytes
#define TILE_B (128 * ROWB)              // 18432 B
#define STAGE_B (2 * TILE_B)             // A | B = 36864 B
#define GEMM_SMEM (2 * STAGE_B)          // 73728 B

__device__ __forceinline__ void load_chunk(uint32_t st,
                                           const __half* A, const __half* B,
                                           int bm, int bn, int k0, int tid)
{
#pragma unroll
    for (int t = 0; t < 4; ++t) {
        int id  = tid + t * 256;         // 0..1023
        int r   = id >> 3;               // row 0..127
        int seg = (id & 7) * 8;          // fp16 elem offset (8 = 16B)
        uint32_t soff = (uint32_t)(r * ROWB + seg * 2);
        cp_async16(st + soff,          A + (size_t)(bm + r) * GK + k0 + seg);
        cp_async16(st + TILE_B + soff, B + (size_t)(bn + r) * GK + k0 + seg);
    }
}

__global__ __launch_bounds__(256, 2)
void gemm_hmma(const float* __restrict__ bq, const float* __restrict__ bk,
               const float* __restrict__ bv)
{
    extern __shared__ __align__(128) char smem[];
    const int tid  = threadIdx.x;
    const int wid  = tid >> 5;
    const int lane = tid & 31;
    const int sel  = blockIdx.x / 6;
    const int nt6  = blockIdx.x % 6;
    const int bm   = blockIdx.y * BM;
    const int bn   = nt6 * BN;
    const int wm   = wid >> 2;           // 0-1
    const int wn   = wid & 3;            // 0-3

    const __half* __restrict__ A = g_Xh;
    const __half* __restrict__ B = g_Wh[sel];
    __half* __restrict__ Ch = (sel == 0) ? g_Qh : (sel == 1) ? g_Kh : g_Vh;
    __half* __restrict__ Cl = (sel == 0) ? g_Ql : (sel == 1) ? g_Kl : g_Vl;
    const float* __restrict__ bias = (sel == 0) ? bq : (sel == 1) ? bk : bv;

    const uint32_t sb = smem_u32(smem);

    float acc[4][4][4];
#pragma unroll
    for (int i = 0; i < 4; i++)
#pragma unroll
        for (int j = 0; j < 4; j++)
#pragma unroll
            for (int u = 0; u < 4; u++) acc[i][j][u] = 0.f;

    load_chunk(sb, A, B, bm, bn, 0, tid);
    CP_COMMIT();
    load_chunk(sb + STAGE_B, A, B, bm, bn, BK, tid);
    CP_COMMIT();

    // A-frag: rows (lane&15), k-half (lane>>4)*8
    const uint32_t a_row  = (uint32_t)(wm * 64 + (lane & 15));
    const uint32_t a_koff = (uint32_t)((lane >> 4) << 3);
    // B-frag x4: n = (lane&7) + ((lane>>4)&1)*8, k = ((lane>>3)&1)*8
    const uint32_t b_row  = (uint32_t)(wn * 32 + (lane & 7) + (((lane >> 4) & 1) << 3));
    const uint32_t b_koff = (uint32_t)(((lane >> 3) & 1) << 3);

    for (int c = 0; c < NCHUNK; ++c) {
        CP_WAIT1();
        __syncthreads();
        const uint32_t st = sb + (uint32_t)(c & 1) * STAGE_B;

#pragma unroll
        for (int ks = 0; ks < 4; ++ks) {
            const uint32_t k0 = ks * 16;
            uint32_t af[4][4], bf[2][4];
#pragma unroll
            for (int mt = 0; mt < 4; ++mt) {
                uint32_t off = ((a_row + mt * 16) * ROWH + k0 + a_koff) * 2;
                ldsm_x4(af[mt], st + off);
            }
#pragma unroll
            for (int ng = 0; ng < 2; ++ng) {
                uint32_t off = ((b_row + ng * 16) * ROWH + k0 + b_koff) * 2;
                ldsm_x4(bf[ng], st + TILE_B + off);
            }
#pragma unroll
            for (int mt = 0; mt < 4; ++mt)
#pragma unroll
                for (int ng = 0; ng < 2; ++ng) {
                    mma16816(acc[mt][2 * ng],     af[mt], bf[ng]);
                    mma16816(acc[mt][2 * ng + 1], af[mt], bf[ng] + 2);
                }
        }

        __syncthreads();
        if (c + 2 < NCHUNK)
            load_chunk(sb + (uint32_t)(c & 1) * STAGE_B, A, B, bm, bn, (c + 2) * BK, tid);
        CP_COMMIT();
    }

    // Epilogue: bias add, fp16 hi/lo split store
#pragma unroll
    for (int nt = 0; nt < 4; ++nt) {
        const int col = bn + wn * 32 + nt * 8 + (lane & 3) * 2;
        const float2 bb = *(const float2*)(bias + col);
#pragma unroll
        for (int mt = 0; mt < 4; ++mt) {
            const int row = bm + wm * 64 + mt * 16 + (lane >> 2);
            float v0 = acc[mt][nt][0] + bb.x;
            float v1 = acc[mt][nt][1] + bb.y;
            float v2 = acc[mt][nt][2] + bb.x;
            float v3 = acc[mt][nt][3] + bb.y;
            size_t i0 = (size_t)row * GN + col;
            size_t i1 = (size_t)(row + 8) * GN + col;
            *(uint32_t*)(Ch + i0) = pack_f16(v0, v1);
            *(uint32_t*)(Cl + i0) = pack_f16(v0 - f16_round(v0), v1 - f16_round(v1));
            *(uint32_t*)(Ch + i1) = pack_f16(v2, v3);
            *(uint32_t*)(Cl + i1) = pack_f16(v2 - f16_round(v2), v3 - f16_round(v3));
        }
    }
}

// ---------------------------------------------------------------------------
// HMMA fused causal flash attention (fp16 hi/lo splits).
// Grid (qt=4, h=12, g=256), 128 threads = 4 warps; warp owns 16 q rows.
// S = Qh.Kh + Qh.Kl + Ql.Kh;  O += Ph.Vh + Pl.Vh + Ph.Vl  (P split in regs).
// ---------------------------------------------------------------------------
#define FSTR 72
#define FTILE_B (64 * FSTR * 2)          // 9216 B per 64x64 fp16 tile
#define FQ_B (2 * FTILE_B)               // Qh | Ql
#define FSTAGE_B (4 * FTILE_B)           // Kh | Kl | Vh | Vl = 36864 B
#define FLASH_SMEM (FQ_B + 2 * FSTAGE_B) // 92160 B

__device__ __forceinline__ void flash_load_tile(uint32_t base, size_t krow0,
                                                int colh, int tid)
{
#pragma unroll
    for (int i = 0; i < 4; ++i) {
        int id  = tid + i * 128;         // 0..511
        int r   = id >> 3;               // row 0..63
        int seg = (id & 7) * 16;         // byte offset in 128B row
        uint32_t soff = (uint32_t)(r * 144 + seg);
        cp_async16(base + soff,              (const char*)(g_Kh + (krow0 + r) * GN + colh) + seg);
        cp_async16(base + FTILE_B + soff,    (const char*)(g_Kl + (krow0 + r) * GN + colh) + seg);
        cp_async16(base + 2 * FTILE_B + soff,(const char*)(g_Vh + (krow0 + r) * GN + colh) + seg);
        cp_async16(base + 3 * FTILE_B + soff,(const char*)(g_Vl + (krow0 + r) * GN + colh) + seg);
    }
}

__global__ __launch_bounds__(128)
void flash_attn_tc(float* __restrict__ O)
{
    extern __shared__ __align__(128) char smem[];
    const int tid  = threadIdx.x;
    const int warp = tid >> 5;
    const int lane = tid & 31;
    const int qt   = blockIdx.x;
    const int h    = blockIdx.y;
    const int g    = blockIdx.z;
    const int colh = h * 64;
    const size_t qrow0 = (size_t)g * 256 + qt * 64;
    const uint32_t sb = smem_u32(smem);

#pragma unroll
    for (int i = 0; i < 4; ++i) {
        int id  = tid + i * 128;
        int r   = id >> 3;
        int seg = (id & 7) * 16;
        uint32_t soff = (uint32_t)(r * 144 + seg);
        cp_async16(sb + soff, (const char*)(g_Qh + (qrow0 + r) * GN + colh) + seg);
        cp_async16(sb + FTILE_B + soff, (const char*)(g_Ql + (qrow0 + r) * GN + colh) + seg);
    }
    flash_load_tile(sb + FQ_B, (size_t)g * 256, colh, tid);
    CP_COMMIT();
    if (qt > 0) flash_load_tile(sb + FQ_B + FSTAGE_B, (size_t)g * 256 + 64, colh, tid);
    CP_COMMIT();

    const int lm = lane >> 3;
    const int lr = lane & 7;
    const int r0 = warp * 16;
    const uint32_t a_off0 = (uint32_t)(((r0 + (lm & 1) * 8 + lr) * FSTR + (lm >> 1) * 8) * 2);
    const uint32_t kb_off0 = (uint32_t)((((lm >> 1) * 8 + lr) * FSTR + (lm & 1) * 8) * 2);
    const uint32_t vb_off0 = (uint32_t)((((lm & 1) * 8 + lr) * FSTR + (lm >> 1) * 8) * 2);

    uint32_t qh[4][4];
    float m_[2] = {-1e30f, -1e30f};
    float l_[2] = {0.f, 0.f};
    float o[8][4];
#pragma unroll
    for (int j = 0; j < 8; ++j)
#pragma unroll
        for (int c = 0; c < 4; ++c) o[j][c] = 0.f;

    const int ra = warp * 16 + (lane >> 2);
    const int rb = ra + 8;

    for (int kt = 0; kt <= qt; ++kt) {
        CP_WAIT1();
        __syncthreads();
        const uint32_t kb = sb + FQ_B + (uint32_t)(kt & 1) * FSTAGE_B;

        if (kt == 0) {
#pragma unroll
            for (int kc = 0; kc < 4; ++kc)
                ldsm_x4(qh[kc], sb + a_off0 + kc * 32);
        }

        float s[8][4];
#pragma unroll
        for (int j = 0; j < 8; ++j)
#pragma unroll
            for (int c = 0; c < 4; ++c) s[j][c] = 0.f;

#pragma unroll
        for (int kc = 0; kc < 4; ++kc) {
            uint32_t qlf[4];
            ldsm_x4(qlf, sb + FTILE_B + a_off0 + kc * 32);
#pragma unroll
            for (int p = 0; p < 4; ++p) {
                uint32_t kh4[4], kl4[4];
                uint32_t off = kb_off0 + (uint32_t)((p * 16 * FSTR + kc * 16) * 2);
                ldsm_x4(kh4, kb + off);
                ldsm_x4(kl4, kb + FTILE_B + off);
                mma16816(s[2 * p],     qh[kc], kh4);
                mma16816(s[2 * p],     qh[kc], kl4);
                mma16816(s[2 * p],     qlf,    kh4);
                mma16816(s[2 * p + 1], qh[kc], kh4 + 2);
                mma16816(s[2 * p + 1], qh[kc], kl4 + 2);
                mma16816(s[2 * p + 1], qlf,    kh4 + 2);
            }
        }

        const float scale = 0.125f;
#pragma unroll
        for (int j = 0; j < 8; ++j)
#pragma unroll
            for (int c = 0; c < 4; ++c) s[j][c] *= scale;
        if (kt == qt) {
#pragma unroll
            for (int j = 0; j < 8; ++j) {
                int k0j = j * 8 + (lane & 3) * 2;
                if (k0j     > ra) s[j][0] = -1e30f;
                if (k0j + 1 > ra) s[j][1] = -1e30f;
                if (k0j     > rb) s[j][2] = -1e30f;
                if (k0j + 1 > rb) s[j][3] = -1e30f;
            }
        }

        float mA = -1e30f, mB = -1e30f;
#pragma unroll
        for (int j = 0; j < 8; ++j) {
            mA = fmaxf(mA, fmaxf(s[j][0], s[j][1]));
            mB = fmaxf(mB, fmaxf(s[j][2], s[j][3]));
        }
        mA = fmaxf(mA, __shfl_xor_sync(0xffffffffu, mA, 1));
        mA = fmaxf(mA, __shfl_xor_sync(0xffffffffu, mA, 2));
        mB = fmaxf(mB, __shfl_xor_sync(0xffffffffu, mB, 1));
        mB = fmaxf(mB, __shfl_xor_sync(0xffffffffu, mB, 2));

        float mnA = fmaxf(m_[0], mA), mnB = fmaxf(m_[1], mB);
        float corrA = __expf(m_[0] - mnA), corrB = __expf(m_[1] - mnB);
        m_[0] = mnA; m_[1] = mnB;

        float rsA = 0.f, rsB = 0.f;
#pragma unroll
        for (int j = 0; j < 8; ++j) {
            s[j][0] = __expf(s[j][0] - mnA);
            s[j][1] = __expf(s[j][1] - mnA);
            s[j][2] = __expf(s[j][2] - mnB);
            s[j][3] = __expf(s[j][3] - mnB);
            rsA += s[j][0] + s[j][1];
            rsB += s[j][2] + s[j][3];
        }
        rsA += __shfl_xor_sync(0xffffffffu, rsA, 1);
        rsA += __shfl_xor_sync(0xffffffffu, rsA, 2);
        rsB += __shfl_xor_sync(0xffffffffu, rsB, 1);
        rsB += __shfl_xor_sync(0xffffffffu, rsB, 2);
        l_[0] = l_[0] * corrA + rsA;
        l_[1] = l_[1] * corrB + rsB;

#pragma unroll
        for (int j = 0; j < 8; ++j) {
            o[j][0] *= corrA; o[j][1] *= corrA;
            o[j][2] *= corrB; o[j][3] *= corrB;
        }

        uint32_t ph[4][4], pl[4][4];
#pragma unroll
        for (int kc = 0; kc < 4; ++kc) {
            int j0 = 2 * kc, j1 = j0 + 1;
            ph[kc][0] = pack_f16(s[j0][0], s[j0][1]);
            ph[kc][1] = pack_f16(s[j0][2], s[j0][3]);
            ph[kc][2] = pack_f16(s[j1][0], s[j1][1]);
            ph[kc][3] = pack_f16(s[j1][2], s[j1][3]);
            pl[kc][0] = pack_f16(s[j0][0] - f16_round(s[j0][0]),
                                 s[j0][1] - f16_round(s[j0][1]));
            pl[kc][1] = pack_f16(s[j0][2] - f16_round(s[j0][2]),
                                 s[j0][3] - f16_round(s[j0][3]));
            pl[kc][2] = pack_f16(s[j1][0] - f16_round(s[j1][0]),
                                 s[j1][1] - f16_round(s[j1][1]));
            pl[kc][3] = pack_f16(s[j1][2] - f16_round(s[j1][2]),
                                 s[j1][3] - f16_round(s[j1][3]));
        }

#pragma unroll
        for (int kc = 0; kc < 4; ++kc) {
#pragma unroll
            for (int p = 0; p < 4; ++p) {
                uint32_t vh4[4], vl4[4];
                uint32_t off = vb_off0 + (uint32_t)((kc * 16 * FSTR + p * 16) * 2);
                ldsm_x4_t(vh4, kb + 2 * FTILE_B + off);
                ldsm_x4_t(vl4, kb + 3 * FTILE_B + off);
                mma16816(o[2 * p],     ph[kc], vh4);
                mma16816(o[2 * p],     pl[kc], vh4);
                mma16816(o[2 * p],     ph[kc], vl4);
                mma16816(o[2 * p + 1], ph[kc], vh4 + 2);
                mma16816(o[2 * p + 1], pl[kc], vh4 + 2);
                mma16816(o[2 * p + 1], ph[kc], vl4 + 2);
            }
        }

        __syncthreads();
        if (kt + 2 <= qt)
            flash_load_tile(sb + FQ_B + (uint32_t)(kt & 1) * FSTAGE_B,
                            (size_t)g * 256 + (kt + 2) * 64, colh, tid);
        CP_COMMIT();
    }

    const float invA = 1.0f / l_[0];
    const float invB = 1.0f / l_[1];
#pragma unroll
    for (int j = 0; j < 8; ++j) {
        const int col = colh + j * 8 + (lane & 3) * 2;
        const size_t rA = qrow0 + warp * 16 + (lane >> 2);
        float2 oa, ob;
        oa.x = o[j][0] * invA; oa.y = o[j][1] * invA;
        ob.x = o[j][2] * invB; ob.y = o[j][3] * invB;
        *(float2*)(O + rA * GN + col) = oa;
        *(float2*)(O + (rA + 8) * GN + col) = ob;
    }
}

// ---------------------------------------------------------------------------
extern "C" void kernel_launch(void* const* d_in, const int* in_sizes, int n_in,
                              void* d_out, int out_size)
{
    const float* X  = (const float*)d_in[0];
    const float* Wq = (const float*)d_in[1];
    const float* bq = (const float*)d_in[2];
    const float* Wk = (const float*)d_in[3];
    const float* bk = (const float*)d_in[4];
    const float* Wv = (const float*)d_in[5];
    const float* bv = (const float*)d_in[6];
    float* O = (float*)d_out;

    __half *xh, *wh;
    cudaGetSymbolAddress((void**)&xh, g_Xh);
    cudaGetSymbolAddress((void**)&wh, g_Wh);

    {
        int n4 = (GM * GK) / 4;
        to_f16<<<(n4 + 255) / 256, 256>>>(X, xh, n4);
        int w4 = (GN * GK) / 4;
        to_f16<<<(w4 + 255) / 256, 256>>>(Wq, wh + 0 * (size_t)GN * GK, w4);
        to_f16<<<(w4 + 255) / 256, 256>>>(Wk, wh + 1 * (size_t)GN * GK, w4);
        to_f16<<<(w4 + 255) / 256, 256>>>(Wv, wh + 2 * (size_t)GN * GK, w4);
    }

    cudaFuncSetAttribute(gemm_hmma, cudaFuncAttributeMaxDynamicSharedMemorySize, GEMM_SMEM);
    dim3 ggrid(18, GM / BM);
    gemm_hmma<<<ggrid, 256, GEMM_SMEM>>>(bq, bk, bv);

    cudaFuncSetAttribute(flash_attn_tc, cudaFuncAttributeMaxDynamicSharedMemorySize, FLASH_SMEM);
    dim3 agrid(4, 12, 256);
    flash_attn_tc<<<agrid, 128, FLASH_SMEM>>>(O);
}

// round 13
// speedup vs baseline: 6.7740x; 1.3247x over previous
#include <cuda_runtime.h>
#include <cuda_fp16.h>
#include <cstdint>
#include <math.h>

#define GM 65536
#define GK 768
#define GN 768

// ---------------------------------------------------------------------------
// Device scratch (allocation-free rule: __device__ globals)
// X/W and Q/K/V: plain fp16 (error budget audited: total ~5e-4 < 1e-3).
// ---------------------------------------------------------------------------
__device__ __half g_Qh[(size_t)GM * GN];
__device__ __half g_Kh[(size_t)GM * GN];
__device__ __half g_Vh[(size_t)GM * GN];
__device__ __half g_Xh[(size_t)GM * GK];
__device__ __half g_Wh[3][(size_t)GN * GK];

// ---------------------------------------------------------------------------
// Baseline-ISA helpers (compute_103-safe)
// ---------------------------------------------------------------------------
__device__ __forceinline__ uint32_t smem_u32(const void* p) {
    uint32_t a;
    asm("{ .reg .u64 t; cvta.to.shared.u64 t, %1; cvt.u32.u64 %0, t; }"
        : "=r"(a) : "l"(p));
    return a;
}

__device__ __forceinline__ void cp_async16(uint32_t saddr, const void* gptr) {
    asm volatile("cp.async.cg.shared.global [%0], [%1], 16;"
                 :: "r"(saddr), "l"(gptr) : "memory");
}
#define CP_COMMIT() asm volatile("cp.async.commit_group;" ::: "memory")
#define CP_WAIT1()  asm volatile("cp.async.wait_group 1;" ::: "memory")

__device__ __forceinline__ void ldsm_x4(uint32_t* r, uint32_t addr) {
    asm volatile("ldmatrix.sync.aligned.m8n8.x4.shared.b16 {%0,%1,%2,%3}, [%4];"
                 : "=r"(r[0]), "=r"(r[1]), "=r"(r[2]), "=r"(r[3]) : "r"(addr));
}
__device__ __forceinline__ void ldsm_x4_t(uint32_t* r, uint32_t addr) {
    asm volatile("ldmatrix.sync.aligned.m8n8.x4.trans.shared.b16 {%0,%1,%2,%3}, [%4];"
                 : "=r"(r[0]), "=r"(r[1]), "=r"(r[2]), "=r"(r[3]) : "r"(addr));
}
// fp16 HMMA, fp32 accumulate
__device__ __forceinline__ void mma16816(float* c, const uint32_t* a, const uint32_t* b) {
    asm volatile(
        "mma.sync.aligned.m16n8k16.row.col.f32.f16.f16.f32 "
        "{%0,%1,%2,%3}, {%4,%5,%6,%7}, {%8,%9}, {%0,%1,%2,%3};"
        : "+f"(c[0]), "+f"(c[1]), "+f"(c[2]), "+f"(c[3])
        : "r"(a[0]), "r"(a[1]), "r"(a[2]), "r"(a[3]), "r"(b[0]), "r"(b[1]));
}
__device__ __forceinline__ uint32_t pack_f16(float lo, float hi) {
    __half2 h = __floats2half2_rn(lo, hi);
    return *(uint32_t*)&h;
}

// ---------------------------------------------------------------------------
// fp32 -> fp16 convert
// ---------------------------------------------------------------------------
__global__ void to_f16(const float* __restrict__ src, __half* __restrict__ dst, int n4)
{
    int i = blockIdx.x * blockDim.x + threadIdx.x;
    if (i >= n4) return;
    float4 v = ((const float4*)src)[i];
    uint32_t* D = (uint32_t*)dst;
    D[2 * i]     = pack_f16(v.x, v.y);
    D[2 * i + 1] = pack_f16(v.z, v.w);
}

// ---------------------------------------------------------------------------
// fp16 single-term HMMA QKV GEMM: C = A @ W^T + bias.
// CTA 128x128, BK=64, 8 warps (2m x 4n), warp tile 64x32.
// smem rows padded to 72 fp16 (144 B) -> conflict-free ldmatrix.
// ---------------------------------------------------------------------------
#define BM 128
#define BN 128
#define BK 64
#define NCHUNK (GK / BK)                 // 12
#define ROWH 72                          // padded row, fp16 elems
#define ROWB 144                         // padded row bytes
#define TILE_B (128 * ROWB)              // 18432 B
#define STAGE_B (2 * TILE_B)             // A | B = 36864 B
#define GEMM_SMEM (2 * STAGE_B)          // 73728 B

__device__ __forceinline__ void load_chunk(uint32_t st,
                                           const __half* A, const __half* B,
                                           int bm, int bn, int k0, int tid)
{
#pragma unroll
    for (int t = 0; t < 4; ++t) {
        int id  = tid + t * 256;         // 0..1023
        int r   = id >> 3;               // row 0..127
        int seg = (id & 7) * 8;          // fp16 elem offset (8 = 16B)
        uint32_t soff = (uint32_t)(r * ROWB + seg * 2);
        cp_async16(st + soff,          A + (size_t)(bm + r) * GK + k0 + seg);
        cp_async16(st + TILE_B + soff, B + (size_t)(bn + r) * GK + k0 + seg);
    }
}

__global__ __launch_bounds__(256, 2)
void gemm_hmma(const float* __restrict__ bq, const float* __restrict__ bk,
               const float* __restrict__ bv)
{
    extern __shared__ __align__(128) char smem[];
    const int tid  = threadIdx.x;
    const int wid  = tid >> 5;
    const int lane = tid & 31;
    const int sel  = blockIdx.x / 6;
    const int nt6  = blockIdx.x % 6;
    const int bm   = blockIdx.y * BM;
    const int bn   = nt6 * BN;
    const int wm   = wid >> 2;           // 0-1
    const int wn   = wid & 3;            // 0-3

    const __half* __restrict__ A = g_Xh;
    const __half* __restrict__ B = g_Wh[sel];
    __half* __restrict__ C = (sel == 0) ? g_Qh : (sel == 1) ? g_Kh : g_Vh;
    const float* __restrict__ bias = (sel == 0) ? bq : (sel == 1) ? bk : bv;

    const uint32_t sb = smem_u32(smem);

    float acc[4][4][4];
#pragma unroll
    for (int i = 0; i < 4; i++)
#pragma unroll
        for (int j = 0; j < 4; j++)
#pragma unroll
            for (int u = 0; u < 4; u++) acc[i][j][u] = 0.f;

    load_chunk(sb, A, B, bm, bn, 0, tid);
    CP_COMMIT();
    load_chunk(sb + STAGE_B, A, B, bm, bn, BK, tid);
    CP_COMMIT();

    const uint32_t a_row  = (uint32_t)(wm * 64 + (lane & 15));
    const uint32_t a_koff = (uint32_t)((lane >> 4) << 3);
    const uint32_t b_row  = (uint32_t)(wn * 32 + (lane & 7) + (((lane >> 4) & 1) << 3));
    const uint32_t b_koff = (uint32_t)(((lane >> 3) & 1) << 3);

    for (int c = 0; c < NCHUNK; ++c) {
        CP_WAIT1();
        __syncthreads();
        const uint32_t st = sb + (uint32_t)(c & 1) * STAGE_B;

#pragma unroll
        for (int ks = 0; ks < 4; ++ks) {
            const uint32_t k0 = ks * 16;
            uint32_t af[4][4], bf[2][4];
#pragma unroll
            for (int mt = 0; mt < 4; ++mt) {
                uint32_t off = ((a_row + mt * 16) * ROWH + k0 + a_koff) * 2;
                ldsm_x4(af[mt], st + off);
            }
#pragma unroll
            for (int ng = 0; ng < 2; ++ng) {
                uint32_t off = ((b_row + ng * 16) * ROWH + k0 + b_koff) * 2;
                ldsm_x4(bf[ng], st + TILE_B + off);
            }
#pragma unroll
            for (int mt = 0; mt < 4; ++mt)
#pragma unroll
                for (int ng = 0; ng < 2; ++ng) {
                    mma16816(acc[mt][2 * ng],     af[mt], bf[ng]);
                    mma16816(acc[mt][2 * ng + 1], af[mt], bf[ng] + 2);
                }
        }

        __syncthreads();
        if (c + 2 < NCHUNK)
            load_chunk(sb + (uint32_t)(c & 1) * STAGE_B, A, B, bm, bn, (c + 2) * BK, tid);
        CP_COMMIT();
    }

    // Epilogue: bias add, fp16 store
#pragma unroll
    for (int nt = 0; nt < 4; ++nt) {
        const int col = bn + wn * 32 + nt * 8 + (lane & 3) * 2;
        const float2 bb = *(const float2*)(bias + col);
#pragma unroll
        for (int mt = 0; mt < 4; ++mt) {
            const int row = bm + wm * 64 + mt * 16 + (lane >> 2);
            size_t i0 = (size_t)row * GN + col;
            size_t i1 = (size_t)(row + 8) * GN + col;
            *(uint32_t*)(C + i0) = pack_f16(acc[mt][nt][0] + bb.x, acc[mt][nt][1] + bb.y);
            *(uint32_t*)(C + i1) = pack_f16(acc[mt][nt][2] + bb.x, acc[mt][nt][3] + bb.y);
        }
    }
}

// ---------------------------------------------------------------------------
// HMMA fused causal flash attention, plain fp16 Q/K/V (single-term MMAs).
// Grid (qt=4, h=12, g=256), 128 threads = 4 warps; warp owns 16 q rows.
// smem: Q (9216 B) | 2 stages x (Kh|Vh) (18432 B each) = 46 KB -> 4 CTAs/SM.
// ---------------------------------------------------------------------------
#define FSTR 72
#define FTILE_B (64 * FSTR * 2)          // 9216 B per 64x64 fp16 tile
#define FQ_B FTILE_B                     // Q tile
#define FSTAGE_B (2 * FTILE_B)           // Kh | Vh = 18432 B
#define FLASH_SMEM (FQ_B + 2 * FSTAGE_B) // 46080 B

__device__ __forceinline__ void flash_load_tile(uint32_t base, size_t krow0,
                                                int colh, int tid)
{
#pragma unroll
    for (int i = 0; i < 4; ++i) {
        int id  = tid + i * 128;         // 0..511
        int r   = id >> 3;               // row 0..63
        int seg = (id & 7) * 16;         // byte offset in 128B data row
        uint32_t soff = (uint32_t)(r * 144 + seg);
        cp_async16(base + soff,           (const char*)(g_Kh + (krow0 + r) * GN + colh) + seg);
        cp_async16(base + FTILE_B + soff, (const char*)(g_Vh + (krow0 + r) * GN + colh) + seg);
    }
}

__global__ __launch_bounds__(128)
void flash_attn_tc(float* __restrict__ O)
{
    extern __shared__ __align__(128) char smem[];
    const int tid  = threadIdx.x;
    const int warp = tid >> 5;
    const int lane = tid & 31;
    const int qt   = blockIdx.x;
    const int h    = blockIdx.y;
    const int g    = blockIdx.z;
    const int colh = h * 64;
    const size_t qrow0 = (size_t)g * 256 + qt * 64;
    const uint32_t sb = smem_u32(smem);

    // Load Q (grouped with tile 0's commit)
#pragma unroll
    for (int i = 0; i < 4; ++i) {
        int id  = tid + i * 128;
        int r   = id >> 3;
        int seg = (id & 7) * 16;
        uint32_t soff = (uint32_t)(r * 144 + seg);
        cp_async16(sb + soff, (const char*)(g_Qh + (qrow0 + r) * GN + colh) + seg);
    }
    flash_load_tile(sb + FQ_B, (size_t)g * 256, colh, tid);
    CP_COMMIT();
    if (qt > 0) flash_load_tile(sb + FQ_B + FSTAGE_B, (size_t)g * 256 + 64, colh, tid);
    CP_COMMIT();

    const int lm = lane >> 3;
    const int lr = lane & 7;
    const int r0 = warp * 16;
    const uint32_t a_off0  = (uint32_t)(((r0 + (lm & 1) * 8 + lr) * FSTR + (lm >> 1) * 8) * 2);
    const uint32_t kb_off0 = (uint32_t)((((lm >> 1) * 8 + lr) * FSTR + (lm & 1) * 8) * 2);
    const uint32_t vb_off0 = (uint32_t)((((lm & 1) * 8 + lr) * FSTR + (lm >> 1) * 8) * 2);

    uint32_t qh[4][4];
    float m_[2] = {-1e30f, -1e30f};
    float l_[2] = {0.f, 0.f};
    float o[8][4];
#pragma unroll
    for (int j = 0; j < 8; ++j)
#pragma unroll
        for (int c = 0; c < 4; ++c) o[j][c] = 0.f;

    const int ra = warp * 16 + (lane >> 2);
    const int rb = ra + 8;

    for (int kt = 0; kt <= qt; ++kt) {
        CP_WAIT1();
        __syncthreads();
        const uint32_t kb = sb + FQ_B + (uint32_t)(kt & 1) * FSTAGE_B;

        if (kt == 0) {
#pragma unroll
            for (int kc = 0; kc < 4; ++kc)
                ldsm_x4(qh[kc], sb + a_off0 + kc * 32);
        }

        // ---- S = Q . K^T ----
        float s[8][4];
#pragma unroll
        for (int j = 0; j < 8; ++j)
#pragma unroll
            for (int c = 0; c < 4; ++c) s[j][c] = 0.f;

#pragma unroll
        for (int kc = 0; kc < 4; ++kc)
#pragma unroll
            for (int p = 0; p < 4; ++p) {
                uint32_t kh4[4];
                uint32_t off = kb_off0 + (uint32_t)((p * 16 * FSTR + kc * 16) * 2);
                ldsm_x4(kh4, kb + off);
                mma16816(s[2 * p],     qh[kc], kh4);
                mma16816(s[2 * p + 1], qh[kc], kh4 + 2);
            }

        // ---- scale + causal mask ----
        const float scale = 0.125f;
#pragma unroll
        for (int j = 0; j < 8; ++j)
#pragma unroll
            for (int c = 0; c < 4; ++c) s[j][c] *= scale;
        if (kt == qt) {
#pragma unroll
            for (int j = 0; j < 8; ++j) {
                int k0j = j * 8 + (lane & 3) * 2;
                if (k0j     > ra) s[j][0] = -1e30f;
                if (k0j + 1 > ra) s[j][1] = -1e30f;
                if (k0j     > rb) s[j][2] = -1e30f;
                if (k0j + 1 > rb) s[j][3] = -1e30f;
            }
        }

        // ---- online softmax ----
        float mA = -1e30f, mB = -1e30f;
#pragma unroll
        for (int j = 0; j < 8; ++j) {
            mA = fmaxf(mA, fmaxf(s[j][0], s[j][1]));
            mB = fmaxf(mB, fmaxf(s[j][2], s[j][3]));
        }
        mA = fmaxf(mA, __shfl_xor_sync(0xffffffffu, mA, 1));
        mA = fmaxf(mA, __shfl_xor_sync(0xffffffffu, mA, 2));
        mB = fmaxf(mB, __shfl_xor_sync(0xffffffffu, mB, 1));
        mB = fmaxf(mB, __shfl_xor_sync(0xffffffffu, mB, 2));

        float mnA = fmaxf(m_[0], mA), mnB = fmaxf(m_[1], mB);
        float corrA = __expf(m_[0] - mnA), corrB = __expf(m_[1] - mnB);
        m_[0] = mnA; m_[1] = mnB;

        float rsA = 0.f, rsB = 0.f;
#pragma unroll
        for (int j = 0; j < 8; ++j) {
            s[j][0] = __expf(s[j][0] - mnA);
            s[j][1] = __expf(s[j][1] - mnA);
            s[j][2] = __expf(s[j][2] - mnB);
            s[j][3] = __expf(s[j][3] - mnB);
            rsA += s[j][0] + s[j][1];
            rsB += s[j][2] + s[j][3];
        }
        rsA += __shfl_xor_sync(0xffffffffu, rsA, 1);
        rsA += __shfl_xor_sync(0xffffffffu, rsA, 2);
        rsB += __shfl_xor_sync(0xffffffffu, rsB, 1);
        rsB += __shfl_xor_sync(0xffffffffu, rsB, 2);
        l_[0] = l_[0] * corrA + rsA;
        l_[1] = l_[1] * corrB + rsB;

#pragma unroll
        for (int j = 0; j < 8; ++j) {
            o[j][0] *= corrA; o[j][1] *= corrA;
            o[j][2] *= corrB; o[j][3] *= corrB;
        }

        // ---- pack P -> fp16 A-frags ----
        uint32_t ph[4][4];
#pragma unroll
        for (int kc = 0; kc < 4; ++kc) {
            int j0 = 2 * kc, j1 = j0 + 1;
            ph[kc][0] = pack_f16(s[j0][0], s[j0][1]);
            ph[kc][1] = pack_f16(s[j0][2], s[j0][3]);
            ph[kc][2] = pack_f16(s[j1][0], s[j1][1]);
            ph[kc][3] = pack_f16(s[j1][2], s[j1][3]);
        }

        // ---- O += P . V ----
#pragma unroll
        for (int kc = 0; kc < 4; ++kc)
#pragma unroll
            for (int p = 0; p < 4; ++p) {
                uint32_t vh4[4];
                uint32_t off = vb_off0 + (uint32_t)((kc * 16 * FSTR + p * 16) * 2);
                ldsm_x4_t(vh4, kb + FTILE_B + off);
                mma16816(o[2 * p],     ph[kc], vh4);
                mma16816(o[2 * p + 1], ph[kc], vh4 + 2);
            }

        __syncthreads();
        if (kt + 2 <= qt)
            flash_load_tile(sb + FQ_B + (uint32_t)(kt & 1) * FSTAGE_B,
                            (size_t)g * 256 + (kt + 2) * 64, colh, tid);
        CP_COMMIT();
    }

    // ---- epilogue ----
    const float invA = 1.0f / l_[0];
    const float invB = 1.0f / l_[1];
#pragma unroll
    for (int j = 0; j < 8; ++j) {
        const int col = colh + j * 8 + (lane & 3) * 2;
        const size_t rA = qrow0 + warp * 16 + (lane >> 2);
        float2 oa, ob;
        oa.x = o[j][0] * invA; oa.y = o[j][1] * invA;
        ob.x = o[j][2] * invB; ob.y = o[j][3] * invB;
        *(float2*)(O + rA * GN + col) = oa;
        *(float2*)(O + (rA + 8) * GN + col) = ob;
    }
}

// ---------------------------------------------------------------------------
extern "C" void kernel_launch(void* const* d_in, const int* in_sizes, int n_in,
                              void* d_out, int out_size)
{
    const float* X  = (const float*)d_in[0];
    const float* Wq = (const float*)d_in[1];
    const float* bq = (const float*)d_in[2];
    const float* Wk = (const float*)d_in[3];
    const float* bk = (const float*)d_in[4];
    const float* Wv = (const float*)d_in[5];
    const float* bv = (const float*)d_in[6];
    float* O = (float*)d_out;

    __half *xh, *wh;
    cudaGetSymbolAddress((void**)&xh, g_Xh);
    cudaGetSymbolAddress((void**)&wh, g_Wh);

    {
        int n4 = (GM * GK) / 4;
        to_f16<<<(n4 + 255) / 256, 256>>>(X, xh, n4);
        int w4 = (GN * GK) / 4;
        to_f16<<<(w4 + 255) / 256, 256>>>(Wq, wh + 0 * (size_t)GN * GK, w4);
        to_f16<<<(w4 + 255) / 256, 256>>>(Wk, wh + 1 * (size_t)GN * GK, w4);
        to_f16<<<(w4 + 255) / 256, 256>>>(Wv, wh + 2 * (size_t)GN * GK, w4);
    }

    cudaFuncSetAttribute(gemm_hmma, cudaFuncAttributeMaxDynamicSharedMemorySize, GEMM_SMEM);
    dim3 ggrid(18, GM / BM);
    gemm_hmma<<<ggrid, 256, GEMM_SMEM>>>(bq, bk, bv);

    cudaFuncSetAttribute(flash_attn_tc, cudaFuncAttributeMaxDynamicSharedMemorySize, FLASH_SMEM);
    dim3 agrid(4, 12, 256);
    flash_attn_tc<<<agrid, 128, FLASH_SMEM>>>(O);
}